// round 16
// baseline (speedup 1.0000x reference)
#include <cuda_runtime.h>
#include <cuda_fp16.h>
#include <cstdint>

#define MAXN 131072
#define MAXE 655360
#define GMAX 1024

// ---------------- static scratch (zero-initialized at module load) ----------------
__device__ __half  g_h[(size_t)MAXN * 128];        // residual stream (fp16)
__device__ __half  g_t[(size_t)MAXN * 128];        // GEMM A operand (fp16)
__device__ __half  g_ecombL[8 * 512 * 128];        // per-layer scaled bond tables s_l*e
__device__ int2    g_epack[MAXE];                  // {src*256, combo*256}, CSR order
__device__ int     g_rowptr[MAXN + 1];
__device__ int     g_deg[MAXN];                    // zeroed by pool-extra blocks
__device__ int     g_cursor[MAXN];                 // zeroed by pool-extra blocks
__device__ int     g_scanagg[128];
__device__ int     g_scanpre[128];
__device__ volatile int g_scanflag[128];           // zeroed by pool-extra blocks
__device__ __half  g_Wt[8 * 128 * 128];            // Wt[l][n][k] = W[l][k][n] (fp16)
__device__ float   g_bnsum[8 * 128];               // zeroed by k_final blocks 0-7
__device__ float   g_bnsq[8 * 128];
__device__ __half  g_asc[128];                     // s_{l+1}-folded BN scale (fp16)
__device__ __half  g_ash[128];                     // s_{l+1}-folded BN shift (fp16)
__device__ int     g_donecnt;                      // gemm last-block counter (self-reset)
__device__ float   g_acc[(size_t)GMAX * 128];      // zeroed by k_final after read
__device__ int     g_cnt[GMAX];

// ---------------- helpers ----------------
__device__ __forceinline__ uint32_t smem_u32(const void* p) {
    uint32_t a;
    asm("{ .reg .u64 t; cvta.to.shared.u64 t, %1; cvt.u32.u64 %0, t; }" : "=r"(a) : "l"(p));
    return a;
}

#define LDMATRIX_X4(r0, r1, r2, r3, addr) \
    asm volatile("ldmatrix.sync.aligned.m8n8.x4.shared.b16 {%0,%1,%2,%3}, [%4];" \
                 : "=r"(r0), "=r"(r1), "=r"(r2), "=r"(r3) : "r"(addr))

#define MMA_F16(c, a0, a1, a2, a3, b0, b1) \
    asm volatile("mma.sync.aligned.m16n8k16.row.col.f32.f16.f16.f32 " \
                 "{%0,%1,%2,%3}, {%4,%5,%6,%7}, {%8,%9}, {%0,%1,%2,%3};" \
                 : "+f"((c)[0]), "+f"((c)[1]), "+f"((c)[2]), "+f"((c)[3]) \
                 : "r"(a0), "r"(a1), "r"(a2), "r"(a3), "r"(b0), "r"(b1))

#define EX2_F16X2(dst, src) \
    asm("ex2.approx.f16x2 %0, %1;" : "=r"(dst) : "r"(src))

#define LOG2E 1.44269504088896f

// ---------------- fused init: convW | ecomb(all layers) | h0 | degree hist --------
__global__ void __launch_bounds__(128) k_init(const int* __restrict__ x,
                                              const float* __restrict__ aemb,
                                              const float* __restrict__ bemb,
                                              const float* __restrict__ w,
                                              const int* __restrict__ ei,
                                              const float* __restrict__ ts,
                                              int N, int E, int L) {
    int b = blockIdx.x;
    int tid = threadIdx.x;
    int gcw = L * 128;
    if (b < gcw) {                       // transpose conv weights -> fp16
        int i = b * 128 + tid;
        int l = i >> 14, r = i & 16383, n = r >> 7, k = r & 127;
        g_Wt[i] = __float2half(w[(l << 14) + (k << 7) + n]);
        return;
    }
    b -= gcw;
    if (b < 512) {                       // combined bond tables, all layers, scaled
        int a0 = b & 7, a1 = (b >> 3) & 7, a2 = (b >> 6) & 7;
        float s = __ldg(bemb + (0 * 8 + a0) * 128 + tid)
                + __ldg(bemb + (1 * 8 + a1) * 128 + tid)
                + __ldg(bemb + (2 * 8 + a2) * 128 + tid);
        for (int l = 0; l < L; l++) {
            float sl = __ldg(ts + l) * LOG2E;
            g_ecombL[(size_t)l * 65536 + b * 128 + tid] = __float2half(s * sl);
        }
        return;
    }
    b -= 512;
    if (b < 1024) {                      // atom encoder, warp per node, float4
        int wid = tid >> 5, lane = tid & 31;
        for (int n = b * 4 + wid; n < N; n += 4096) {
            float4 sum = make_float4(0.f, 0.f, 0.f, 0.f);
#pragma unroll
            for (int f = 0; f < 9; f++) {
                int xi = __ldg(x + n * 9 + f);
                float4 v = __ldg((const float4*)(aemb + ((size_t)f * 64 + xi) * 128) + lane);
                sum.x += v.x; sum.y += v.y; sum.z += v.z; sum.w += v.w;
            }
            __half2 a01 = __floats2half2_rn(sum.x, sum.y);
            __half2 a23 = __floats2half2_rn(sum.z, sum.w);
            uint2 hv;
            hv.x = *reinterpret_cast<uint32_t*>(&a01);
            hv.y = *reinterpret_cast<uint32_t*>(&a23);
            *(uint2*)(g_h + (size_t)n * 128 + lane * 4) = hv;
        }
        return;
    }
    b -= 1024;
    for (int e = b * 128 + tid; e < E; e += 2048 * 128)
        atomicAdd(g_deg + __ldg(ei + E + e), 1);
}

// ---------------- single-kernel decoupled-lookback exclusive scan ----------------
__global__ void __launch_bounds__(1024) k_scan(int N, int E) {
    __shared__ int warp_tot[32];
    __shared__ int s_prefix;
    int b = blockIdx.x, tid = threadIdx.x, lane = tid & 31, wid = tid >> 5;
    int i = b * 1024 + tid;
    int v = (i < N) ? g_deg[i] : 0;
    int xv = v;
#pragma unroll
    for (int o = 1; o < 32; o <<= 1) {
        int y = __shfl_up_sync(0xFFFFFFFFu, xv, o);
        if (lane >= o) xv += y;
    }
    if (lane == 31) warp_tot[wid] = xv;
    __syncthreads();
    if (wid == 0) {
        int wv = warp_tot[lane];
#pragma unroll
        for (int o = 1; o < 32; o <<= 1) {
            int y = __shfl_up_sync(0xFFFFFFFFu, wv, o);
            if (lane >= o) wv += y;
        }
        warp_tot[lane] = wv;
    }
    __syncthreads();
    int woff = wid ? warp_tot[wid - 1] : 0;
    int incl = woff + xv;
    int total = warp_tot[31];
    if (tid == 0) {
        g_scanagg[b] = total;
        __threadfence();
        g_scanflag[b] = 1;
        int sum = 0;
        for (int j = b - 1; j >= 0; j--) {
            int f;
            while ((f = g_scanflag[j]) == 0) {}
            if (f == 2) { sum += ((volatile int*)g_scanpre)[j]; break; }
            sum += ((volatile int*)g_scanagg)[j];
        }
        g_scanpre[b] = sum + total;
        __threadfence();
        g_scanflag[b] = 2;
        s_prefix = sum;
    }
    __syncthreads();
    int excl = s_prefix + incl - v;
    if (i < N) g_rowptr[i] = excl;
    if (i == N - 1) g_rowptr[N] = E;
}

// ---------------- scatter edges into CSR order (byte-offset packed) ----------------
__global__ void k_scatter(const int* __restrict__ ei, const int* __restrict__ ea, int E) {
    int e = blockIdx.x * blockDim.x + threadIdx.x;
    if (e >= E) return;
    int d = __ldg(ei + E + e);
    int pos = g_rowptr[d] + atomicAdd(g_cursor + d, 1);
    int a0 = __ldg(ea + e * 3 + 0), a1 = __ldg(ea + e * 3 + 1), a2 = __ldg(ea + e * 3 + 2);
    g_epack[pos] = make_int2(__ldg(ei + e) << 8, (a0 + a1 * 8 + a2 * 64) << 8);
}

// ------ softmax aggregation: warp/node, inline BN affine, f16x2, paired epack ------
// FIRST=1: layer 0 (no BN, no relu on h):  q = max(s*h_src + s*e, 0)
// FIRST=0: q = max( max(ssc*h_src+ssh, 0) + s*e, 0 )
template<int FIRST>
__global__ void __launch_bounds__(256) k_agg(const float* __restrict__ ts, int l, int N) {
    int gw = (blockIdx.x << 3) + (threadIdx.x >> 5);
    if (gw >= N) return;
    int lane = threadIdx.x & 31;
    const char* ph = (const char*)g_h + lane * 8;
    const char* pe = (const char*)(g_ecombL + (size_t)l * 65536) + lane * 8;
    float s = __ldg(ts + l) * LOG2E;
    float invs = 1.0f / s;
    __half2 neg6 = __float2half2_rn(-6.0f);
    __half2 z = __float2half2_rn(0.f);

    __half2 sc01, sc23, sh01, sh23;
    if (FIRST) {
        sc01 = __float2half2_rn(s);
        sc23 = sc01;
        sh01 = z; sh23 = z;
    } else {
        uint2 scv = *(const uint2*)((const char*)g_asc + lane * 8);
        uint2 shv = *(const uint2*)((const char*)g_ash + lane * 8);
        sc01 = *(__half2*)&scv.x; sc23 = *(__half2*)&scv.y;
        sh01 = *(__half2*)&shv.x; sh23 = *(__half2*)&shv.y;
    }

    uint2 hu = *(const uint2*)(ph + (size_t)gw * 256);
    __half2 hd01 = *(__half2*)&hu.x, hd23 = *(__half2*)&hu.y;
    __half2 hin01, hin23;
    if (FIRST) {
        hin01 = __hmul2(hd01, sc01);
        hin23 = __hmul2(hd23, sc23);
    } else {
        hin01 = __hmax2(__hfma2(hd01, sc01, sh01), z);
        hin23 = __hmax2(__hfma2(hd23, sc23, sh23), z);
    }
    float2 hi01 = __half22float2(hin01), hi23 = __half22float2(hin23);

    int p0 = __ldg(g_rowptr + gw), p1 = __ldg(g_rowptr + gw + 1);
    __half2 s01 = z, s23 = z, w01 = z, w23 = z;

    // one edge body (macro-free lambda)
    auto edge = [&](int sx, int ex) {
        uint2 su = *(const uint2*)(ph + sx);
        uint2 eu = *(const uint2*)(pe + ex);
        __half2 q01, q23;
        if (FIRST) {
            q01 = __hmax2(__hfma2(*(__half2*)&su.x, sc01, *(__half2*)&eu.x), z);
            q23 = __hmax2(__hfma2(*(__half2*)&su.y, sc23, *(__half2*)&eu.y), z);
        } else {
            __half2 t01 = __hmax2(__hfma2(*(__half2*)&su.x, sc01, sh01), z);
            __half2 t23 = __hmax2(__hfma2(*(__half2*)&su.y, sc23, sh23), z);
            q01 = __hmax2(__hadd2(t01, *(__half2*)&eu.x), z);
            q23 = __hmax2(__hadd2(t23, *(__half2*)&eu.y), z);
        }
        __half2 a01 = __hadd2(q01, neg6);
        __half2 a23 = __hadd2(q23, neg6);
        uint32_t x01u, x23u;
        EX2_F16X2(x01u, *reinterpret_cast<uint32_t*>(&a01));
        EX2_F16X2(x23u, *reinterpret_cast<uint32_t*>(&a23));
        __half2 x01 = *reinterpret_cast<__half2*>(&x01u);
        __half2 x23 = *reinterpret_cast<__half2*>(&x23u);
        s01 = __hadd2(s01, x01);
        s23 = __hadd2(s23, x23);
        w01 = __hfma2(x01, q01, w01);
        w23 = __hfma2(x23, q23, w23);
    };

    int p = p0;
    if (p < p1 && (p & 1)) {             // align to 16B for int4 pair loads
        int2 ep = __ldg(g_epack + p);
        edge(ep.x, ep.y);
        p++;
    }
    for (; p + 2 <= p1; p += 2) {
        int4 ep2 = __ldg((const int4*)(g_epack + p));   // two edges, one LDG.128
        edge(ep2.x, ep2.y);
        edge(ep2.z, ep2.w);
    }
    if (p < p1) {
        int2 ep = __ldg(g_epack + p);
        edge(ep.x, ep.y);
    }

    float2 sf01 = __half22float2(s01), sf23 = __half22float2(s23);
    float2 wf01 = __half22float2(w01), wf23 = __half22float2(w23);
    float o0 = (hi01.x + wf01.x / (sf01.x + 1e-16f)) * invs;
    float o1 = (hi01.y + wf01.y / (sf01.y + 1e-16f)) * invs;
    float o2 = (hi23.x + wf23.x / (sf23.x + 1e-16f)) * invs;
    float o3 = (hi23.y + wf23.y / (sf23.y + 1e-16f)) * invs;

    __half2 t01 = __floats2half2_rn(o0, o1);
    __half2 t23 = __floats2half2_rn(o2, o3);
    uint2 st;
    st.x = *reinterpret_cast<uint32_t*>(&t01);
    st.y = *reinterpret_cast<uint32_t*>(&t23);
    *(uint2*)(g_t + (size_t)gw * 128 + lane * 4) = st;
}

// ------- mma.sync GEMM + fused BN stats + last-block computes next-layer affine -------
#define GEMM_SMEM (2 * 128 * 272 + 1024)

__global__ void __launch_bounds__(256) k_gemm(const float* __restrict__ conv_b,
                                              const float* __restrict__ gammas,
                                              const float* __restrict__ betas,
                                              const float* __restrict__ ts,
                                              int l, int add_res, int N, int L,
                                              float invN) {
    extern __shared__ char smem[];
    char* sA = smem;
    char* sB = smem + 128 * 272;
    float* sbn = (float*)(smem + 2 * 128 * 272);
    __shared__ int s_islast;
    int tid = threadIdx.x;
    int node0 = blockIdx.x * 128;

    if (tid < 256) sbn[tid] = 0.f;

    const uint4* asrc = (const uint4*)(g_t + (size_t)node0 * 128);
    const uint4* bsrc = (const uint4*)(g_Wt + (size_t)l * 16384);
#pragma unroll
    for (int i = tid; i < 2048; i += 256) {
        int row = i >> 4, cq = i & 15;
        *(uint4*)(sA + row * 272 + cq * 16) = asrc[i];
        *(uint4*)(sB + row * 272 + cq * 16) = bsrc[i];
    }
    __syncthreads();

    int wid = tid >> 5, lane = tid & 31;
    int wm = wid >> 1, wn = wid & 1;
    uint32_t sab = smem_u32(sA), sbb = smem_u32(sB);

    float acc[2][8][4];
#pragma unroll
    for (int mt = 0; mt < 2; mt++)
#pragma unroll
        for (int nt = 0; nt < 8; nt++)
#pragma unroll
            for (int q = 0; q < 4; q++) acc[mt][nt][q] = 0.f;

    int lrow = lane & 15, lhalf = (lane >> 4) << 3;

#pragma unroll
    for (int ks = 0; ks < 8; ks++) {
        int k0 = ks * 16;
        uint32_t a[2][4];
#pragma unroll
        for (int mt = 0; mt < 2; mt++) {
            int r = wm * 32 + mt * 16 + lrow;
            uint32_t addr = sab + r * 272 + (k0 + lhalf) * 2;
            LDMATRIX_X4(a[mt][0], a[mt][1], a[mt][2], a[mt][3], addr);
        }
        uint32_t bq[4][4];
#pragma unroll
        for (int nq = 0; nq < 4; nq++) {
            int nr = wn * 64 + nq * 16 + lrow;
            uint32_t addr = sbb + nr * 272 + (k0 + lhalf) * 2;
            LDMATRIX_X4(bq[nq][0], bq[nq][1], bq[nq][2], bq[nq][3], addr);
        }
#pragma unroll
        for (int mt = 0; mt < 2; mt++)
#pragma unroll
            for (int nq = 0; nq < 4; nq++) {
                MMA_F16(acc[mt][nq * 2 + 0], a[mt][0], a[mt][1], a[mt][2], a[mt][3],
                        bq[nq][0], bq[nq][2]);
                MMA_F16(acc[mt][nq * 2 + 1], a[mt][0], a[mt][1], a[mt][2], a[mt][3],
                        bq[nq][1], bq[nq][3]);
            }
    }

    int qrow = lane >> 2, qcol = (lane & 3) * 2;
    float colS[16], colQ[16];
#pragma unroll
    for (int i = 0; i < 16; i++) { colS[i] = 0.f; colQ[i] = 0.f; }

#pragma unroll
    for (int mt = 0; mt < 2; mt++) {
#pragma unroll
        for (int nt = 0; nt < 8; nt++) {
            int col = wn * 64 + nt * 8 + qcol;
            float2 bv = *(const float2*)(conv_b + l * 128 + col);
            int row0 = node0 + wm * 32 + mt * 16 + qrow;
#pragma unroll
            for (int hh = 0; hh < 2; hh++) {
                int row = row0 + hh * 8;
                if (row < N) {
                    __half* dst = g_h + (size_t)row * 128 + col;
                    float vx = acc[mt][nt][hh * 2 + 0] + bv.x;
                    float vy = acc[mt][nt][hh * 2 + 1] + bv.y;
                    if (add_res) {
                        float2 r = __half22float2(*(const __half2*)dst);
                        vx += r.x; vy += r.y;
                    }
                    *(__half2*)dst = __floats2half2_rn(vx, vy);
                    colS[nt * 2 + 0] += vx;
                    colQ[nt * 2 + 0] = fmaf(vx, vx, colQ[nt * 2 + 0]);
                    colS[nt * 2 + 1] += vy;
                    colQ[nt * 2 + 1] = fmaf(vy, vy, colQ[nt * 2 + 1]);
                }
            }
        }
    }

#pragma unroll
    for (int i = 0; i < 16; i++) {
        float vs = colS[i], vq = colQ[i];
        vs += __shfl_xor_sync(0xFFFFFFFFu, vs, 4);
        vs += __shfl_xor_sync(0xFFFFFFFFu, vs, 8);
        vs += __shfl_xor_sync(0xFFFFFFFFu, vs, 16);
        vq += __shfl_xor_sync(0xFFFFFFFFu, vq, 4);
        vq += __shfl_xor_sync(0xFFFFFFFFu, vq, 8);
        vq += __shfl_xor_sync(0xFFFFFFFFu, vq, 16);
        if (lane < 4) {
            int col = wn * 64 + (i >> 1) * 8 + lane * 2 + (i & 1);
            atomicAdd(sbn + col, vs);
            atomicAdd(sbn + 128 + col, vq);
        }
    }
    __syncthreads();
    if (tid < 128) {
        atomicAdd(g_bnsum + l * 128 + tid, sbn[tid]);
        atomicAdd(g_bnsq + l * 128 + tid, sbn[128 + tid]);
    }

    // last block computes the s_{l+1}-folded BN affine for the next agg
    if (l + 1 < L) {
        __threadfence();
        if (tid == 0) {
            int c = atomicAdd(&g_donecnt, 1);
            s_islast = (c == (int)gridDim.x - 1);
        }
        __syncthreads();
        if (s_islast) {
            if (tid < 128) {
                float sm = __ldcg(g_bnsum + l * 128 + tid);
                float sq = __ldcg(g_bnsq + l * 128 + tid);
                float mu = sm * invN;
                float var = sq * invN - mu * mu;
                float sc = rsqrtf(var + 1e-5f) * __ldg(gammas + l * 128 + tid);
                float sh = __ldg(betas + l * 128 + tid) - mu * sc;
                float sn = __ldg(ts + l + 1) * LOG2E;
                g_asc[tid] = __float2half(sc * sn);
                g_ash[tid] = __float2half(sh * sn);
            }
            if (tid == 0) g_donecnt = 0;
        }
    }
}

// ---------------- pooling (final BN inline) + prologue-state cleanup ----------------
__global__ void k_pool(const int* __restrict__ batch, const float* __restrict__ gammas,
                       const float* __restrict__ betas, int l, int N, int nlen,
                       float invN, int P) {
    if ((int)blockIdx.x >= P) {
        int base = (blockIdx.x - P) * 128 + threadIdx.x;
        for (int j = base; j < N; j += 16 * 128) { g_deg[j] = 0; g_cursor[j] = 0; }
        if (base < 128) g_scanflag[base] = 0;
        return;
    }
    int c = threadIdx.x;
    int n0 = blockIdx.x * nlen, n1 = min(N, n0 + nlen);
    if (n0 >= n1) return;
    float sm = g_bnsum[l * 128 + c], sq = g_bnsq[l * 128 + c];
    float mu = sm * invN;
    float var = sq * invN - mu * mu;
    float sc = rsqrtf(var + 1e-5f) * __ldg(gammas + l * 128 + c);
    float sh = __ldg(betas + l * 128 + c) - mu * sc;
    int cur = __ldg(batch + n0);
    float acc = 0.f;
    int cnt = 0;
    for (int n = n0; n < n1; n++) {
        int gg = __ldg(batch + n);
        if (gg != cur) {
            atomicAdd(g_acc + (size_t)cur * 128 + c, acc);
            if (c == 0) atomicAdd(g_cnt + cur, cnt);
            acc = 0.f; cnt = 0; cur = gg;
        }
        float hv = __half2float(g_h[(size_t)n * 128 + c]);
        float v = fmaxf(fmaf(hv, sc, sh), 0.f);
        acc += v;
        cnt++;
    }
    atomicAdd(g_acc + (size_t)cur * 128 + c, acc);
    if (c == 0) atomicAdd(g_cnt + cur, cnt);
}

// ---------------- head + remaining cleanup ----------------
__global__ void k_final(const float* __restrict__ fw, const float* __restrict__ fb,
                        const float* __restrict__ beta, const float* __restrict__ rf,
                        float* __restrict__ out, int G) {
    int wid = threadIdx.x >> 5, lane = threadIdx.x & 31;
    if (blockIdx.x < 8) {
        g_bnsum[blockIdx.x * 128 + threadIdx.x] = 0.f;
        g_bnsq[blockIdx.x * 128 + threadIdx.x] = 0.f;
    }
    int g = blockIdx.x * 4 + wid;
    if (g >= G) return;
    float4 a = ((const float4*)(g_acc + (size_t)g * 128))[lane];
    float4 w = ((const float4*)fw)[lane];
    float dot = a.x * w.x + a.y * w.y + a.z * w.z + a.w * w.w;
#pragma unroll
    for (int o = 16; o > 0; o >>= 1) dot += __shfl_down_sync(0xFFFFFFFFu, dot, o);
    int cntv = g_cnt[g];
    ((float4*)(g_acc + (size_t)g * 128))[lane] = make_float4(0.f, 0.f, 0.f, 0.f);
    if (lane == 0) {
        g_cnt[g] = 0;
        float cntf = fmaxf((float)cntv, 1.f);
        float pred = dot / cntf + fb[0];
        float sg = 1.f / (1.f + __expf(-pred));
        float b = beta[0];
        out[g] = (1.f - b) * sg + b * rf[g];
    }
}

// ---------------- launch ----------------
extern "C" void kernel_launch(void* const* d_in, const int* in_sizes, int n_in,
                              void* d_out, int out_size) {
    const int*   x      = (const int*)d_in[0];
    const int*   ei     = (const int*)d_in[1];
    const int*   ea     = (const int*)d_in[2];
    const int*   batch  = (const int*)d_in[3];
    const float* rf     = (const float*)d_in[4];
    const float* aemb   = (const float*)d_in[5];
    const float* bemb   = (const float*)d_in[6];
    const float* convw  = (const float*)d_in[7];
    const float* convb  = (const float*)d_in[8];
    const float* ts     = (const float*)d_in[9];
    const float* gammas = (const float*)d_in[10];
    const float* betas  = (const float*)d_in[11];
    const float* fw     = (const float*)d_in[12];
    const float* fb     = (const float*)d_in[13];
    const float* beta   = (const float*)d_in[14];
    float* out = (float*)d_out;

    int N = in_sizes[0] / 9;
    int E = in_sizes[1] / 2;
    int G = in_sizes[4];
    int L = in_sizes[9];
    float invN = 1.f / (float)N;

    cudaFuncSetAttribute(k_gemm, cudaFuncAttributeMaxDynamicSharedMemorySize, GEMM_SMEM);

    int agg_grid = (N + 7) / 8;
    int gemm_grid = (N + 127) / 128;
    int nb = (N + 1023) / 1024;   // 98 blocks <= 148 SMs (lookback-safe)

    k_init<<<L * 128 + 512 + 1024 + 2048, 128>>>(x, aemb, bemb, convw, ei, ts, N, E, L);
    k_scan<<<nb, 1024>>>(N, E);
    k_scatter<<<(E + 255) / 256, 256>>>(ei, ea, E);

    k_agg<1><<<agg_grid, 256>>>(ts, 0, N);       // launch index 3 -> ncu target
    k_gemm<<<gemm_grid, 256, GEMM_SMEM>>>(convb, gammas, betas, ts, 0, 0, N, L, invN);

    for (int l = 1; l < L; l++) {
        k_agg<0><<<agg_grid, 256>>>(ts, l, N);
        k_gemm<<<gemm_grid, 256, GEMM_SMEM>>>(convb, gammas, betas, ts, l, 1, N, L, invN);
    }

    int P = 512;
    int nlen = (N + P - 1) / P;
    k_pool<<<P + 16, 128>>>(batch, gammas, betas, L - 1, N, nlen, invN, P);
    k_final<<<(G + 3) / 4, 128>>>(fw, fb, beta, rf, out, G);
}

// round 17
// speedup vs baseline: 1.5330x; 1.5330x over previous
#include <cuda_runtime.h>
#include <cuda_fp16.h>
#include <cstdint>

#define MAXN 131072
#define MAXE 655360
#define GMAX 1024

// ---------------- static scratch (zero-initialized at module load) ----------------
__device__ __half  g_h[(size_t)MAXN * 128];        // residual stream (fp16)
__device__ __half  g_t[(size_t)MAXN * 128];        // GEMM A operand (fp16)
__device__ __half  g_ecombL[8 * 512 * 128];        // per-layer scaled bond tables s_l*e
__device__ int2    g_epack[MAXE];                  // {src*256, combo*256}, CSR order
__device__ int     g_rowptr[MAXN + 1];
__device__ int     g_deg[MAXN];                    // zeroed by pool-extra blocks
__device__ int     g_cursor[MAXN];                 // zeroed by pool-extra blocks
__device__ int     g_scanagg[128];
__device__ int     g_scanpre[128];
__device__ volatile int g_scanflag[128];           // zeroed by pool-extra blocks
__device__ __half  g_Wt[8 * 128 * 128];            // Wt[l][n][k] = W[l][k][n] (fp16)
__device__ float   g_bnsum[8 * 128];               // zeroed by k_final blocks 0-7
__device__ float   g_bnsq[8 * 128];
__device__ __half  g_asc[128];                     // s_{l+1}-folded BN scale (fp16)
__device__ __half  g_ash[128];                     // s_{l+1}-folded BN shift (fp16)
__device__ int     g_donecnt;                      // gemm last-block counter (self-reset)
__device__ float   g_acc[(size_t)GMAX * 128];      // zeroed by k_final after read
__device__ int     g_cnt[GMAX];

// ---------------- helpers ----------------
__device__ __forceinline__ uint32_t smem_u32(const void* p) {
    uint32_t a;
    asm("{ .reg .u64 t; cvta.to.shared.u64 t, %1; cvt.u32.u64 %0, t; }" : "=r"(a) : "l"(p));
    return a;
}

#define LDMATRIX_X4(r0, r1, r2, r3, addr) \
    asm volatile("ldmatrix.sync.aligned.m8n8.x4.shared.b16 {%0,%1,%2,%3}, [%4];" \
                 : "=r"(r0), "=r"(r1), "=r"(r2), "=r"(r3) : "r"(addr))

#define MMA_F16(c, a0, a1, a2, a3, b0, b1) \
    asm volatile("mma.sync.aligned.m16n8k16.row.col.f32.f16.f16.f32 " \
                 "{%0,%1,%2,%3}, {%4,%5,%6,%7}, {%8,%9}, {%0,%1,%2,%3};" \
                 : "+f"((c)[0]), "+f"((c)[1]), "+f"((c)[2]), "+f"((c)[3]) \
                 : "r"(a0), "r"(a1), "r"(a2), "r"(a3), "r"(b0), "r"(b1))

#define EX2_F16X2(dst, src) \
    asm("ex2.approx.f16x2 %0, %1;" : "=r"(dst) : "r"(src))

#define LOG2E 1.44269504088896f

// ---------------- fused init: convW | ecomb(all layers) | h0 | degree hist --------
__global__ void __launch_bounds__(128) k_init(const int* __restrict__ x,
                                              const float* __restrict__ aemb,
                                              const float* __restrict__ bemb,
                                              const float* __restrict__ w,
                                              const int* __restrict__ ei,
                                              const float* __restrict__ ts,
                                              int N, int E, int L) {
    int b = blockIdx.x;
    int tid = threadIdx.x;
    int gcw = L * 128;
    if (b < gcw) {                       // transpose conv weights -> fp16
        int i = b * 128 + tid;
        int l = i >> 14, r = i & 16383, n = r >> 7, k = r & 127;
        g_Wt[i] = __float2half(w[(l << 14) + (k << 7) + n]);
        return;
    }
    b -= gcw;
    if (b < 512) {                       // combined bond tables, all layers, scaled
        int a0 = b & 7, a1 = (b >> 3) & 7, a2 = (b >> 6) & 7;
        float s = __ldg(bemb + (0 * 8 + a0) * 128 + tid)
                + __ldg(bemb + (1 * 8 + a1) * 128 + tid)
                + __ldg(bemb + (2 * 8 + a2) * 128 + tid);
        for (int l = 0; l < L; l++) {
            float sl = __ldg(ts + l) * LOG2E;
            g_ecombL[(size_t)l * 65536 + b * 128 + tid] = __float2half(s * sl);
        }
        return;
    }
    b -= 512;
    if (b < 1024) {                      // atom encoder, warp per node, float4
        int wid = tid >> 5, lane = tid & 31;
        for (int n = b * 4 + wid; n < N; n += 4096) {
            float4 sum = make_float4(0.f, 0.f, 0.f, 0.f);
#pragma unroll
            for (int f = 0; f < 9; f++) {
                int xi = __ldg(x + n * 9 + f);
                float4 v = __ldg((const float4*)(aemb + ((size_t)f * 64 + xi) * 128) + lane);
                sum.x += v.x; sum.y += v.y; sum.z += v.z; sum.w += v.w;
            }
            __half2 a01 = __floats2half2_rn(sum.x, sum.y);
            __half2 a23 = __floats2half2_rn(sum.z, sum.w);
            uint2 hv;
            hv.x = *reinterpret_cast<uint32_t*>(&a01);
            hv.y = *reinterpret_cast<uint32_t*>(&a23);
            *(uint2*)(g_h + (size_t)n * 128 + lane * 4) = hv;
        }
        return;
    }
    b -= 1024;
    for (int e = b * 128 + tid; e < E; e += 2048 * 128)
        atomicAdd(g_deg + __ldg(ei + E + e), 1);
}

// ---------------- single-kernel decoupled-lookback exclusive scan ----------------
__global__ void __launch_bounds__(1024) k_scan(int N, int E) {
    __shared__ int warp_tot[32];
    __shared__ int s_prefix;
    int b = blockIdx.x, tid = threadIdx.x, lane = tid & 31, wid = tid >> 5;
    int i = b * 1024 + tid;
    int v = (i < N) ? g_deg[i] : 0;
    int xv = v;
#pragma unroll
    for (int o = 1; o < 32; o <<= 1) {
        int y = __shfl_up_sync(0xFFFFFFFFu, xv, o);
        if (lane >= o) xv += y;
    }
    if (lane == 31) warp_tot[wid] = xv;
    __syncthreads();
    if (wid == 0) {
        int wv = warp_tot[lane];
#pragma unroll
        for (int o = 1; o < 32; o <<= 1) {
            int y = __shfl_up_sync(0xFFFFFFFFu, wv, o);
            if (lane >= o) wv += y;
        }
        warp_tot[lane] = wv;
    }
    __syncthreads();
    int woff = wid ? warp_tot[wid - 1] : 0;
    int incl = woff + xv;
    int total = warp_tot[31];
    if (tid == 0) {
        g_scanagg[b] = total;
        __threadfence();
        g_scanflag[b] = 1;
        int sum = 0;
        for (int j = b - 1; j >= 0; j--) {
            int f;
            while ((f = g_scanflag[j]) == 0) {}
            if (f == 2) { sum += ((volatile int*)g_scanpre)[j]; break; }
            sum += ((volatile int*)g_scanagg)[j];
        }
        g_scanpre[b] = sum + total;
        __threadfence();
        g_scanflag[b] = 2;
        s_prefix = sum;
    }
    __syncthreads();
    int excl = s_prefix + incl - v;
    if (i < N) g_rowptr[i] = excl;
    if (i == N - 1) g_rowptr[N] = E;
}

// ---------------- scatter edges into CSR order (byte-offset packed) ----------------
__global__ void k_scatter(const int* __restrict__ ei, const int* __restrict__ ea, int E) {
    int e = blockIdx.x * blockDim.x + threadIdx.x;
    if (e >= E) return;
    int d = __ldg(ei + E + e);
    int pos = g_rowptr[d] + atomicAdd(g_cursor + d, 1);
    int a0 = __ldg(ea + e * 3 + 0), a1 = __ldg(ea + e * 3 + 1), a2 = __ldg(ea + e * 3 + 2);
    g_epack[pos] = make_int2(__ldg(ei + e) << 8, (a0 + a1 * 8 + a2 * 64) << 8);
}

// ------ softmax aggregation: warp/node, inline BN affine, f16x2 (R12 shape) ------
// FIRST=1: layer 0 (no BN, no relu on h):  q = max(s*h_src + s*e, 0)
// FIRST=0: q = max( max(ssc*h_src+ssh, 0) + s*e, 0 )
template<int FIRST>
__global__ void __launch_bounds__(128) k_agg(const float* __restrict__ ts, int l, int N) {
    int gw = (blockIdx.x << 2) + (threadIdx.x >> 5);
    if (gw >= N) return;
    int lane = threadIdx.x & 31;
    const char* ph = (const char*)g_h + lane * 8;
    const char* pe = (const char*)(g_ecombL + (size_t)l * 65536) + lane * 8;
    float s = __ldg(ts + l) * LOG2E;
    float invs = 1.0f / s;
    __half2 neg6 = __float2half2_rn(-6.0f);
    __half2 z = __float2half2_rn(0.f);

    __half2 sc01, sc23, sh01, sh23;
    if (FIRST) {
        sc01 = __float2half2_rn(s);
        sc23 = sc01;
        sh01 = z; sh23 = z;
    } else {
        uint2 scv = *(const uint2*)((const char*)g_asc + lane * 8);
        uint2 shv = *(const uint2*)((const char*)g_ash + lane * 8);
        sc01 = *(__half2*)&scv.x; sc23 = *(__half2*)&scv.y;
        sh01 = *(__half2*)&shv.x; sh23 = *(__half2*)&shv.y;
    }

    // dst hin in scaled space
    uint2 hu = *(const uint2*)(ph + (size_t)gw * 256);
    __half2 hd01 = *(__half2*)&hu.x, hd23 = *(__half2*)&hu.y;
    __half2 hin01, hin23;
    if (FIRST) {
        hin01 = __hmul2(hd01, sc01);
        hin23 = __hmul2(hd23, sc23);
    } else {
        hin01 = __hmax2(__hfma2(hd01, sc01, sh01), z);
        hin23 = __hmax2(__hfma2(hd23, sc23, sh23), z);
    }
    float2 hi01 = __half22float2(hin01), hi23 = __half22float2(hin23);

    int p0 = __ldg(g_rowptr + gw), p1 = __ldg(g_rowptr + gw + 1);
    __half2 s01 = z, s23 = z, w01 = z, w23 = z;

#pragma unroll 4
    for (int p = p0; p < p1; p++) {
        int2 ep = __ldg(g_epack + p);
        uint2 su = *(const uint2*)(ph + ep.x);
        uint2 eu = *(const uint2*)(pe + ep.y);
        __half2 q01, q23;
        if (FIRST) {
            q01 = __hmax2(__hfma2(*(__half2*)&su.x, sc01, *(__half2*)&eu.x), z);
            q23 = __hmax2(__hfma2(*(__half2*)&su.y, sc23, *(__half2*)&eu.y), z);
        } else {
            __half2 t01 = __hmax2(__hfma2(*(__half2*)&su.x, sc01, sh01), z);
            __half2 t23 = __hmax2(__hfma2(*(__half2*)&su.y, sc23, sh23), z);
            q01 = __hmax2(__hadd2(t01, *(__half2*)&eu.x), z);
            q23 = __hmax2(__hadd2(t23, *(__half2*)&eu.y), z);
        }
        __half2 a01 = __hadd2(q01, neg6);      // exp-bias: x = 2^(q-6)
        __half2 a23 = __hadd2(q23, neg6);
        uint32_t x01u, x23u;
        EX2_F16X2(x01u, *reinterpret_cast<uint32_t*>(&a01));
        EX2_F16X2(x23u, *reinterpret_cast<uint32_t*>(&a23));
        __half2 x01 = *reinterpret_cast<__half2*>(&x01u);
        __half2 x23 = *reinterpret_cast<__half2*>(&x23u);
        s01 = __hadd2(s01, x01);
        s23 = __hadd2(s23, x23);
        w01 = __hfma2(x01, q01, w01);          // positive-definite accumulation
        w23 = __hfma2(x23, q23, w23);
    }

    float2 sf01 = __half22float2(s01), sf23 = __half22float2(s23);
    float2 wf01 = __half22float2(w01), wf23 = __half22float2(w23);
    float o0 = (hi01.x + __fdividef(wf01.x, sf01.x + 1e-16f)) * invs;
    float o1 = (hi01.y + __fdividef(wf01.y, sf01.y + 1e-16f)) * invs;
    float o2 = (hi23.x + __fdividef(wf23.x, sf23.x + 1e-16f)) * invs;
    float o3 = (hi23.y + __fdividef(wf23.y, sf23.y + 1e-16f)) * invs;

    __half2 t01 = __floats2half2_rn(o0, o1);
    __half2 t23 = __floats2half2_rn(o2, o3);
    uint2 st;
    st.x = *reinterpret_cast<uint32_t*>(&t01);
    st.y = *reinterpret_cast<uint32_t*>(&t23);
    *(uint2*)(g_t + (size_t)gw * 128 + lane * 4) = st;
}

// ------- mma.sync GEMM + fused BN stats + last-block computes next-layer affine -------
#define GEMM_SMEM (2 * 128 * 272 + 1024)

__global__ void __launch_bounds__(256) k_gemm(const float* __restrict__ conv_b,
                                              const float* __restrict__ gammas,
                                              const float* __restrict__ betas,
                                              const float* __restrict__ ts,
                                              int l, int add_res, int N, int L,
                                              float invN) {
    extern __shared__ char smem[];
    char* sA = smem;
    char* sB = smem + 128 * 272;
    float* sbn = (float*)(smem + 2 * 128 * 272);
    __shared__ int s_islast;
    int tid = threadIdx.x;
    int node0 = blockIdx.x * 128;

    if (tid < 256) sbn[tid] = 0.f;

    const uint4* asrc = (const uint4*)(g_t + (size_t)node0 * 128);
    const uint4* bsrc = (const uint4*)(g_Wt + (size_t)l * 16384);
#pragma unroll
    for (int i = tid; i < 2048; i += 256) {
        int row = i >> 4, cq = i & 15;
        *(uint4*)(sA + row * 272 + cq * 16) = asrc[i];
        *(uint4*)(sB + row * 272 + cq * 16) = bsrc[i];
    }
    __syncthreads();

    int wid = tid >> 5, lane = tid & 31;
    int wm = wid >> 1, wn = wid & 1;
    uint32_t sab = smem_u32(sA), sbb = smem_u32(sB);

    float acc[2][8][4];
#pragma unroll
    for (int mt = 0; mt < 2; mt++)
#pragma unroll
        for (int nt = 0; nt < 8; nt++)
#pragma unroll
            for (int q = 0; q < 4; q++) acc[mt][nt][q] = 0.f;

    int lrow = lane & 15, lhalf = (lane >> 4) << 3;

#pragma unroll
    for (int ks = 0; ks < 8; ks++) {
        int k0 = ks * 16;
        uint32_t a[2][4];
#pragma unroll
        for (int mt = 0; mt < 2; mt++) {
            int r = wm * 32 + mt * 16 + lrow;
            uint32_t addr = sab + r * 272 + (k0 + lhalf) * 2;
            LDMATRIX_X4(a[mt][0], a[mt][1], a[mt][2], a[mt][3], addr);
        }
        uint32_t bq[4][4];
#pragma unroll
        for (int nq = 0; nq < 4; nq++) {
            int nr = wn * 64 + nq * 16 + lrow;
            uint32_t addr = sbb + nr * 272 + (k0 + lhalf) * 2;
            LDMATRIX_X4(bq[nq][0], bq[nq][1], bq[nq][2], bq[nq][3], addr);
        }
#pragma unroll
        for (int mt = 0; mt < 2; mt++)
#pragma unroll
            for (int nq = 0; nq < 4; nq++) {
                MMA_F16(acc[mt][nq * 2 + 0], a[mt][0], a[mt][1], a[mt][2], a[mt][3],
                        bq[nq][0], bq[nq][2]);
                MMA_F16(acc[mt][nq * 2 + 1], a[mt][0], a[mt][1], a[mt][2], a[mt][3],
                        bq[nq][1], bq[nq][3]);
            }
    }

    int qrow = lane >> 2, qcol = (lane & 3) * 2;
    float colS[16], colQ[16];
#pragma unroll
    for (int i = 0; i < 16; i++) { colS[i] = 0.f; colQ[i] = 0.f; }

#pragma unroll
    for (int mt = 0; mt < 2; mt++) {
#pragma unroll
        for (int nt = 0; nt < 8; nt++) {
            int col = wn * 64 + nt * 8 + qcol;
            float2 bv = *(const float2*)(conv_b + l * 128 + col);
            int row0 = node0 + wm * 32 + mt * 16 + qrow;
#pragma unroll
            for (int hh = 0; hh < 2; hh++) {
                int row = row0 + hh * 8;
                if (row < N) {
                    __half* dst = g_h + (size_t)row * 128 + col;
                    float vx = acc[mt][nt][hh * 2 + 0] + bv.x;
                    float vy = acc[mt][nt][hh * 2 + 1] + bv.y;
                    if (add_res) {
                        float2 r = __half22float2(*(const __half2*)dst);
                        vx += r.x; vy += r.y;
                    }
                    *(__half2*)dst = __floats2half2_rn(vx, vy);
                    colS[nt * 2 + 0] += vx;
                    colQ[nt * 2 + 0] = fmaf(vx, vx, colQ[nt * 2 + 0]);
                    colS[nt * 2 + 1] += vy;
                    colQ[nt * 2 + 1] = fmaf(vy, vy, colQ[nt * 2 + 1]);
                }
            }
        }
    }

#pragma unroll
    for (int i = 0; i < 16; i++) {
        float vs = colS[i], vq = colQ[i];
        vs += __shfl_xor_sync(0xFFFFFFFFu, vs, 4);
        vs += __shfl_xor_sync(0xFFFFFFFFu, vs, 8);
        vs += __shfl_xor_sync(0xFFFFFFFFu, vs, 16);
        vq += __shfl_xor_sync(0xFFFFFFFFu, vq, 4);
        vq += __shfl_xor_sync(0xFFFFFFFFu, vq, 8);
        vq += __shfl_xor_sync(0xFFFFFFFFu, vq, 16);
        if (lane < 4) {
            int col = wn * 64 + (i >> 1) * 8 + lane * 2 + (i & 1);
            atomicAdd(sbn + col, vs);
            atomicAdd(sbn + 128 + col, vq);
        }
    }
    __syncthreads();
    if (tid < 128) {
        atomicAdd(g_bnsum + l * 128 + tid, sbn[tid]);
        atomicAdd(g_bnsq + l * 128 + tid, sbn[128 + tid]);
    }

    // last block computes the s_{l+1}-folded BN affine for the next agg
    if (l + 1 < L) {
        __threadfence();
        if (tid == 0) {
            int c = atomicAdd(&g_donecnt, 1);
            s_islast = (c == (int)gridDim.x - 1);
        }
        __syncthreads();
        if (s_islast) {
            if (tid < 128) {
                float sm = __ldcg(g_bnsum + l * 128 + tid);
                float sq = __ldcg(g_bnsq + l * 128 + tid);
                float mu = sm * invN;
                float var = sq * invN - mu * mu;
                float sc = rsqrtf(var + 1e-5f) * __ldg(gammas + l * 128 + tid);
                float sh = __ldg(betas + l * 128 + tid) - mu * sc;
                float sn = __ldg(ts + l + 1) * LOG2E;
                g_asc[tid] = __float2half(sc * sn);
                g_ash[tid] = __float2half(sh * sn);
            }
            if (tid == 0) g_donecnt = 0;
        }
    }
}

// ---------------- pooling (final BN inline) + prologue-state cleanup ----------------
__global__ void k_pool(const int* __restrict__ batch, const float* __restrict__ gammas,
                       const float* __restrict__ betas, int l, int N, int nlen,
                       float invN, int P) {
    if ((int)blockIdx.x >= P) {
        int base = (blockIdx.x - P) * 128 + threadIdx.x;
        for (int j = base; j < N; j += 16 * 128) { g_deg[j] = 0; g_cursor[j] = 0; }
        if (base < 128) g_scanflag[base] = 0;
        return;
    }
    int c = threadIdx.x;
    int n0 = blockIdx.x * nlen, n1 = min(N, n0 + nlen);
    if (n0 >= n1) return;
    float sm = g_bnsum[l * 128 + c], sq = g_bnsq[l * 128 + c];
    float mu = sm * invN;
    float var = sq * invN - mu * mu;
    float sc = rsqrtf(var + 1e-5f) * __ldg(gammas + l * 128 + c);
    float sh = __ldg(betas + l * 128 + c) - mu * sc;
    int cur = __ldg(batch + n0);
    float acc = 0.f;
    int cnt = 0;
    for (int n = n0; n < n1; n++) {
        int gg = __ldg(batch + n);
        if (gg != cur) {
            atomicAdd(g_acc + (size_t)cur * 128 + c, acc);
            if (c == 0) atomicAdd(g_cnt + cur, cnt);
            acc = 0.f; cnt = 0; cur = gg;
        }
        float hv = __half2float(g_h[(size_t)n * 128 + c]);
        float v = fmaxf(fmaf(hv, sc, sh), 0.f);
        acc += v;
        cnt++;
    }
    atomicAdd(g_acc + (size_t)cur * 128 + c, acc);
    if (c == 0) atomicAdd(g_cnt + cur, cnt);
}

// ---------------- head + remaining cleanup ----------------
__global__ void k_final(const float* __restrict__ fw, const float* __restrict__ fb,
                        const float* __restrict__ beta, const float* __restrict__ rf,
                        float* __restrict__ out, int G) {
    int wid = threadIdx.x >> 5, lane = threadIdx.x & 31;
    if (blockIdx.x < 8) {
        g_bnsum[blockIdx.x * 128 + threadIdx.x] = 0.f;
        g_bnsq[blockIdx.x * 128 + threadIdx.x] = 0.f;
    }
    int g = blockIdx.x * 4 + wid;
    if (g >= G) return;
    float4 a = ((const float4*)(g_acc + (size_t)g * 128))[lane];
    float4 w = ((const float4*)fw)[lane];
    float dot = a.x * w.x + a.y * w.y + a.z * w.z + a.w * w.w;
#pragma unroll
    for (int o = 16; o > 0; o >>= 1) dot += __shfl_down_sync(0xFFFFFFFFu, dot, o);
    int cntv = g_cnt[g];
    ((float4*)(g_acc + (size_t)g * 128))[lane] = make_float4(0.f, 0.f, 0.f, 0.f);
    if (lane == 0) {
        g_cnt[g] = 0;
        float cntf = fmaxf((float)cntv, 1.f);
        float pred = dot / cntf + fb[0];
        float sg = 1.f / (1.f + __expf(-pred));
        float b = beta[0];
        out[g] = (1.f - b) * sg + b * rf[g];
    }
}

// ---------------- launch ----------------
extern "C" void kernel_launch(void* const* d_in, const int* in_sizes, int n_in,
                              void* d_out, int out_size) {
    const int*   x      = (const int*)d_in[0];
    const int*   ei     = (const int*)d_in[1];
    const int*   ea     = (const int*)d_in[2];
    const int*   batch  = (const int*)d_in[3];
    const float* rf     = (const float*)d_in[4];
    const float* aemb   = (const float*)d_in[5];
    const float* bemb   = (const float*)d_in[6];
    const float* convw  = (const float*)d_in[7];
    const float* convb  = (const float*)d_in[8];
    const float* ts     = (const float*)d_in[9];
    const float* gammas = (const float*)d_in[10];
    const float* betas  = (const float*)d_in[11];
    const float* fw     = (const float*)d_in[12];
    const float* fb     = (const float*)d_in[13];
    const float* beta   = (const float*)d_in[14];
    float* out = (float*)d_out;

    int N = in_sizes[0] / 9;
    int E = in_sizes[1] / 2;
    int G = in_sizes[4];
    int L = in_sizes[9];
    float invN = 1.f / (float)N;

    cudaFuncSetAttribute(k_gemm, cudaFuncAttributeMaxDynamicSharedMemorySize, GEMM_SMEM);

    int agg_grid = (N + 3) / 4;
    int gemm_grid = (N + 127) / 128;
    int nb = (N + 1023) / 1024;   // 98 blocks <= 148 SMs (lookback-safe)

    k_init<<<L * 128 + 512 + 1024 + 2048, 128>>>(x, aemb, bemb, convw, ei, ts, N, E, L);
    k_scan<<<nb, 1024>>>(N, E);
    k_scatter<<<(E + 255) / 256, 256>>>(ei, ea, E);

    k_agg<1><<<agg_grid, 128>>>(ts, 0, N);       // launch index 3 -> ncu target
    k_gemm<<<gemm_grid, 256, GEMM_SMEM>>>(convb, gammas, betas, ts, 0, 0, N, L, invN);

    for (int l = 1; l < L; l++) {
        k_agg<0><<<agg_grid, 128>>>(ts, l, N);
        k_gemm<<<gemm_grid, 256, GEMM_SMEM>>>(convb, gammas, betas, ts, l, 1, N, L, invN);
    }

    int P = 512;
    int nlen = (N + P - 1) / P;
    k_pool<<<P + 16, 128>>>(batch, gammas, betas, L - 1, N, nlen, invN, P);
    k_final<<<(G + 3) / 4, 128>>>(fw, fb, beta, rf, out, G);
}